// round 2
// baseline (speedup 1.0000x reference)
#include <cuda_runtime.h>
#include <cuda_bf16.h>
#include <math.h>

// Problem constants
#define B_    8
#define NPIX_ 256
#define M_    8192
#define NCP_  24576
#define NCA_  24576
#define EPSF  1e-16f

// Output layout (tuple flattened in order): vis(B,2,M), visamp(B,M), cphase(B,NCP), logcamp(B,NCA)
#define OFF_AMP (B_*2*M_)                 // 131072
#define OFF_CPH (OFF_AMP + B_*M_)         // 196608
#define OFF_LC  (OFF_CPH + B_*NCP_)       // 393216

// Precomputed phase tables (device globals: no cudaMalloc allowed)
// Ev stored y-major transposed:  g_Ev_t[y*M + m] = exp(-i*kv[m]*(y-128))
// Eu stored m-major:             g_Eu[m*NPIX + x] = exp(-i*ku[m]*(x-128))
__device__ float2 g_Ev_t[NPIX_ * M_];
__device__ float2 g_Eu[M_ * NPIX_];

// ---------- packed f32x2 helpers (sm_103a FFMA2 path) ----------
__device__ __forceinline__ unsigned long long pk2(float lo, float hi) {
    unsigned long long r;
    asm("mov.b64 %0, {%1, %2};" : "=l"(r) : "f"(lo), "f"(hi));
    return r;
}
__device__ __forceinline__ void upk2(unsigned long long v, float& lo, float& hi) {
    asm("mov.b64 {%0, %1}, %2;" : "=f"(lo), "=f"(hi) : "l"(v));
}
__device__ __forceinline__ unsigned long long ffma2(unsigned long long a,
                                                    unsigned long long b,
                                                    unsigned long long c) {
    unsigned long long d;
    asm("fma.rn.f32x2 %0, %1, %2, %3;" : "=l"(d) : "l"(a), "l"(b), "l"(c));
    return d;
}

// ---------- kernel 1: build phase tables ----------
__global__ void k_tables(const float* __restrict__ ktraj) {
    int idx = blockIdx.x * blockDim.x + threadIdx.x;
    if (idx >= M_ * NPIX_) return;
    // Ev (y-major): idx = y*M + m
    {
        int y = idx >> 13;          // / M_ (8192)
        int m = idx & (M_ - 1);
        float c = (float)(y - NPIX_ / 2);
        float s, co;
        sincosf(ktraj[m] * c, &s, &co);      // kv = ktraj[0,:]
        g_Ev_t[idx] = make_float2(co, -s);   // exp(-i*theta)
    }
    // Eu (m-major): idx = m*NPIX + x
    {
        int m = idx >> 8;           // / NPIX_
        int x = idx & (NPIX_ - 1);
        float c = (float)(x - NPIX_ / 2);
        float s, co;
        sincosf(ktraj[M_ + m] * c, &s, &co); // ku = ktraj[1,:]
        g_Eu[idx] = make_float2(co, -s);
    }
}

// ---------- kernel 2: fused DFT + pulsefac + vis/visamp ----------
// grid: (M/16, B), block: 256 threads.
// Thread (tm = t>>6 in [0,4), tx = t&63 in [0,64)) owns m in {m0+tm*4+i}, x in {tx*4+j}.
__global__ void __launch_bounds__(256) k_main(const float* __restrict__ img,
                                              const float* __restrict__ pulse,
                                              float* __restrict__ out) {
    const int m0 = blockIdx.x * 16;
    const int b  = blockIdx.y;
    const int t  = threadIdx.x;
    const int tm = t >> 6;
    const int tx = t & 63;

    __shared__ float2 Evs[NPIX_][16];     // 32 KB: Ev tile, (y, mi)
    __shared__ float  imgs[8][NPIX_];     // 8 KB: 8 image rows
    __shared__ float2 sm_part[8][4];      // per-warp x-reduction partials

    // Load Ev tile: 4096 float2
    for (int k = t; k < NPIX_ * 16; k += 256) {
        int y = k >> 4, mi = k & 15;
        Evs[y][mi] = g_Ev_t[y * M_ + m0 + mi];
    }

    unsigned long long acc[4][4];         // packed (re, im) accumulators
#pragma unroll
    for (int i = 0; i < 4; i++)
#pragma unroll
        for (int j = 0; j < 4; j++) acc[i][j] = 0ull;

    const float4* gimg = (const float4*)(img + (size_t)b * NPIX_ * NPIX_);
    float4* s4 = (float4*)imgs;

    for (int yb = 0; yb < NPIX_ / 8; yb++) {
        __syncthreads();                          // previous block consumed (also fences Ev load on yb=0)
        s4[t]       = gimg[yb * 512 + t];
        s4[t + 256] = gimg[yb * 512 + t + 256];
        __syncthreads();
#pragma unroll
        for (int yy = 0; yy < 8; yy++) {
            const int y = yb * 8 + yy;
            const float4* ep = (const float4*)&Evs[y][tm * 4];
            float4 ea = ep[0], eb = ep[1];
            float4 iv = ((const float4*)imgs[yy])[tx];
            unsigned long long ev[4] = { pk2(ea.x, ea.y), pk2(ea.z, ea.w),
                                         pk2(eb.x, eb.y), pk2(eb.z, eb.w) };
            unsigned long long q[4]  = { pk2(iv.x, iv.x), pk2(iv.y, iv.y),
                                         pk2(iv.z, iv.z), pk2(iv.w, iv.w) };
#pragma unroll
            for (int i = 0; i < 4; i++)
#pragma unroll
                for (int j = 0; j < 4; j++)
                    acc[i][j] = ffma2(ev[i], q[j], acc[i][j]);
        }
    }

    // Phase 2: x-contraction with Eu (complex * complex)
    float kr[4] = {0.f, 0.f, 0.f, 0.f};
    float ki[4] = {0.f, 0.f, 0.f, 0.f};
#pragma unroll
    for (int i = 0; i < 4; i++) {
        const int m = m0 + tm * 4 + i;
        const float4* up = (const float4*)&g_Eu[m * NPIX_ + tx * 4];
        float4 u0 = up[0], u1 = up[1];
        float ur[4] = {u0.x, u0.z, u1.x, u1.z};
        float ui[4] = {u0.y, u0.w, u1.y, u1.w};
#pragma unroll
        for (int j = 0; j < 4; j++) {
            float ar, ai;
            upk2(acc[i][j], ar, ai);
            kr[i] = fmaf(ar, ur[j], fmaf(-ai, ui[j], kr[i]));
            ki[i] = fmaf(ar, ui[j], fmaf(ai, ur[j], ki[i]));
        }
    }

    // Reduce across the 64 threads (2 warps) that share tm
#pragma unroll
    for (int i = 0; i < 4; i++) {
#pragma unroll
        for (int off = 16; off; off >>= 1) {
            kr[i] += __shfl_xor_sync(0xFFFFFFFFu, kr[i], off);
            ki[i] += __shfl_xor_sync(0xFFFFFFFFu, ki[i], off);
        }
    }
    const int wid = t >> 5;
    if ((t & 31) == 0) {
#pragma unroll
        for (int i = 0; i < 4; i++) sm_part[wid][i] = make_float2(kr[i], ki[i]);
    }
    __syncthreads();

    if (t < 16) {
        const int i = t & 3, tmg = t >> 2;
        float2 pa = sm_part[tmg * 2][i], pb = sm_part[tmg * 2 + 1][i];
        float r0 = pa.x + pb.x;
        float i0 = pa.y + pb.y;
        const int m = m0 + t;                  // tmg*4 + i == t
        float p0 = pulse[m], p1 = pulse[M_ + m];
        float vr = r0 * p0 - i0 * p1;
        float vi = r0 * p1 + i0 * p0;
        out[(size_t)b * 2 * M_ + m]      = vr;
        out[(size_t)b * 2 * M_ + M_ + m] = vi;
        out[OFF_AMP + (size_t)b * M_ + m] = sqrtf(vr * vr + vi * vi + EPSF);
    }
}

// ---------- kernel 3: closure phases ----------
__global__ void k_cphase(const float* __restrict__ vis,    // == out base
                         const float* __restrict__ sign,
                         const int* __restrict__ ind,
                         float* __restrict__ out) {
    int idx = blockIdx.x * blockDim.x + threadIdx.x;
    if (idx >= B_ * NCP_) return;
    const int n = idx % NCP_;
    const int b = idx / NCP_;
    const size_t vb = (size_t)b * 2 * M_;
    float s = 0.f;
#pragma unroll
    for (int k = 0; k < 3; k++) {
        int i = ind[k * NCP_ + n];
        float re = vis[vb + i];
        float im = vis[vb + M_ + i];
        s += sign[k * NCP_ + n] * atan2f(im, re);
    }
    out[OFF_CPH + idx] = s * 57.29577951308232f;   // 180/pi
}

// ---------- kernel 4: log closure amplitudes ----------
__global__ void k_logcamp(const float* __restrict__ vis,
                          const int* __restrict__ ind,
                          float* __restrict__ out) {
    int idx = blockIdx.x * blockDim.x + threadIdx.x;
    if (idx >= B_ * NCA_) return;
    const int n = idx % NCA_;
    const int b = idx / NCA_;
    const size_t vb = (size_t)b * 2 * M_;
    float v = 0.f;
#pragma unroll
    for (int k = 0; k < 4; k++) {
        int i = ind[k * NCA_ + n];
        float re = vis[vb + i];
        float im = vis[vb + M_ + i];
        float la = 0.5f * logf(re * re + im * im + EPSF);  // log(sqrt(x)) = 0.5*log(x)
        v += (k < 2) ? la : -la;
    }
    out[OFF_LC + idx] = v;
}

extern "C" void kernel_launch(void* const* d_in, const int* in_sizes, int n_in,
                              void* d_out, int out_size) {
    const float* images = (const float*)d_in[0];   // (B, NPIX, NPIX)
    const float* ktraj  = (const float*)d_in[1];   // (2, M)
    const float* pulse  = (const float*)d_in[2];   // (2, M)
    const float* csign  = (const float*)d_in[3];   // (3, NCP) float
    const int*   cind   = (const int*)d_in[4];     // (3, NCP) int32
    const int*   qind   = (const int*)d_in[5];     // (4, NCA) int32
    float* out = (float*)d_out;

    k_tables<<<(M_ * NPIX_ + 255) / 256, 256>>>(ktraj);

    dim3 grid(M_ / 16, B_);
    k_main<<<grid, 256>>>(images, pulse, out);

    k_cphase<<<(B_ * NCP_ + 255) / 256, 256>>>(out, csign, cind, out);
    k_logcamp<<<(B_ * NCA_ + 255) / 256, 256>>>(out, qind, out);
}

// round 5
// speedup vs baseline: 1.7565x; 1.7565x over previous
#include <cuda_runtime.h>
#include <cuda_bf16.h>
#include <math.h>
#include <stdint.h>

// Problem constants
#define B_    8
#define NPIX_ 256
#define M_    8192
#define NCP_  24576
#define NCA_  24576
#define EPSF  1e-16f

// Output layout: vis(B,2,M), visamp(B,M), cphase(B,NCP), logcamp(B,NCA)
#define OFF_AMP (B_*2*M_)
#define OFF_CPH (OFF_AMP + B_*M_)
#define OFF_LC  (OFF_CPH + B_*NCP_)

// GEMM config
#define MT      64           // m-tile
#define KSEG    256
#define KTOT    768          // split-3: A[hi|lo|hi] * B[hi|hi|lo]
#define KSTAGE  64
#define NSTG    12

// Device-global operands (no cudaMalloc allowed)
// A planes: [comp(2)][part(2: hi,lo)][m][y] bf16
__device__ __nv_bfloat16 g_A[4 * M_ * NPIX_];
// B: [b][x][k=768] bf16 (k = y:hi | y:hi | y:lo)
__device__ __nv_bfloat16 g_B[B_ * NPIX_ * KTOT];
// Eu tables: [m][0..15]=exp(-i*ku*(16j-128)), [m][16..31]=exp(-i*ku*j)
__device__ float2 g_EuCF[M_ * 32];

// SMEM layout (dynamic): rows padded 128B->144B for conflict-free LDS frags
#define ROWB    144
#define A_BUF   (2 * MT * ROWB)            // 18432
#define B_BUF   (NPIX_ * ROWB)             // 36864
#define STAGEB  (A_BUF + B_BUF)            // 55296
#define SM_EUC  (2 * STAGEB)               // 110592
#define SM_EUF  (SM_EUC + 8192)            // 118784
#define SM_PART (SM_EUF + 8192)            // 126976
#define SM_TOTAL (SM_PART + 4096)          // 131072

// ---------------- helpers ----------------
__device__ __forceinline__ uint32_t smem_u32(const void* p) {
    uint32_t a;
    asm("{ .reg .u64 t; cvta.to.shared.u64 t, %1; cvt.u32.u64 %0, t; }" : "=r"(a) : "l"(p));
    return a;
}
__device__ __forceinline__ void cp16(uint32_t dst, const void* src) {
    asm volatile("cp.async.cg.shared.global [%0], [%1], 16;" :: "r"(dst), "l"(src));
}
__device__ __forceinline__ void cp_commit() { asm volatile("cp.async.commit_group;" ::: "memory"); }
template <int N> __device__ __forceinline__ void cp_wait() {
    asm volatile("cp.async.wait_group %0;" :: "n"(N) : "memory");
}
__device__ __forceinline__ void mma_bf16(float* dd, const uint32_t* a, uint32_t b0, uint32_t b1) {
    asm volatile(
        "mma.sync.aligned.m16n8k16.row.col.f32.bf16.bf16.f32 "
        "{%0,%1,%2,%3}, {%4,%5,%6,%7}, {%8,%9}, {%0,%1,%2,%3};"
        : "+f"(dd[0]), "+f"(dd[1]), "+f"(dd[2]), "+f"(dd[3])
        : "r"(a[0]), "r"(a[1]), "r"(a[2]), "r"(a[3]), "r"(b0), "r"(b1));
}

// ---------------- kernel 1: phase tables + Ev bf16 split planes ----------------
__global__ void k_tables(const float* __restrict__ ktraj) {
    int idx = blockIdx.x * blockDim.x + threadIdx.x;
    if (idx < M_ * NPIX_) {
        int m = idx >> 8, y = idx & 255;
        float s, c;
        sincosf(ktraj[m] * (float)(y - NPIX_ / 2), &s, &c);    // kv
        float re = c, im = -s;
        __nv_bfloat16 rh = __float2bfloat16(re);
        __nv_bfloat16 rl = __float2bfloat16(re - __bfloat162float(rh));
        __nv_bfloat16 ih = __float2bfloat16(im);
        __nv_bfloat16 il = __float2bfloat16(im - __bfloat162float(ih));
        g_A[0 * M_ * NPIX_ + idx] = rh;
        g_A[1 * M_ * NPIX_ + idx] = rl;
        g_A[2 * M_ * NPIX_ + idx] = ih;
        g_A[3 * M_ * NPIX_ + idx] = il;
        return;
    }
    idx -= M_ * NPIX_;
    if (idx < M_ * 32) {
        int m = idx >> 5, j = idx & 31;
        float ku = ktraj[M_ + m];
        float ang = (j < 16) ? ku * (float)(16 * j - 128) : ku * (float)(j - 16);
        float s, c;
        sincosf(ang, &s, &c);
        g_EuCF[idx] = make_float2(c, -s);
    }
}

// ---------------- kernel 2: img -> transposed split B ----------------
__global__ void k_split(const float* __restrict__ img) {
    __shared__ float tbuf[32][33];
    const int b = blockIdx.z, x0 = blockIdx.x * 32, y0 = blockIdx.y * 32;
    const int tx = threadIdx.x, ty = threadIdx.y;    // 32 x 8
    const float* ib = img + (size_t)b * NPIX_ * NPIX_;
#pragma unroll
    for (int r = 0; r < 4; r++)
        tbuf[ty + 8 * r][tx] = ib[(y0 + ty + 8 * r) * NPIX_ + x0 + tx];
    __syncthreads();
    __nv_bfloat16* ob = g_B + (size_t)b * NPIX_ * KTOT;
#pragma unroll
    for (int r = 0; r < 4; r++) {
        int x = x0 + ty + 8 * r;
        int y = y0 + tx;
        float v = tbuf[tx][ty + 8 * r];
        __nv_bfloat16 hi = __float2bfloat16(v);
        __nv_bfloat16 lo = __float2bfloat16(v - __bfloat162float(hi));
        __nv_bfloat16* row = ob + (size_t)x * KTOT;
        row[y] = hi;
        row[KSEG + y] = hi;
        row[2 * KSEG + y] = lo;
    }
}

// ---------------- kernel 3: HMMA DFT + fused epilogue ----------------
// 512 threads = 16 warps: comp = wid&1, xw = (wid>>1)&3, mw = wid>>3
// warp tile: 32m x 64x, one complex component. Accum: 64 f32/thread.
__global__ void __launch_bounds__(512, 1) k_main(const float* __restrict__ pulse,
                                                 float* __restrict__ out) {
    extern __shared__ char sm[];
    const uint32_t smb = smem_u32(sm);
    const int t = threadIdx.x;
    const int m0 = blockIdx.x * MT;
    const int b  = blockIdx.y;
    const int wid = t >> 5, lane = t & 31;
    const int comp = wid & 1, xw = (wid >> 1) & 3, mw = wid >> 3;
    const int rq = lane >> 2, qk = lane & 3;

    // Stage Eu tables (region disjoint from K-stage buffers)
    for (int i = t; i < MT * 16; i += 512) {
        int m = i >> 4, j = i & 15;
        ((float2*)(sm + SM_EUC))[i] = g_EuCF[(size_t)(m0 + m) * 32 + j];
        ((float2*)(sm + SM_EUF))[i] = g_EuCF[(size_t)(m0 + m) * 32 + 16 + j];
    }

    const __nv_bfloat16* gB = g_B + (size_t)b * NPIX_ * KTOT;

    // ---- cp.async stage issue: 3072 x 16B chunks, 6 per thread ----
    auto issue = [&](int p, int s) {
        const int seg = s >> 2;
        const int y0  = (s & 3) * KSTAGE;
        const int part = (seg == 1) ? 1 : 0;
        const uint32_t base = smb + p * STAGEB;
#pragma unroll
        for (int it = 0; it < 6; it++) {
            int c = t + it * 512;
            if (c < 1024) {
                int cc = c >> 9, r = (c >> 3) & 63, q = c & 7;
                cp16(base + cc * (MT * ROWB) + r * ROWB + q * 16,
                     g_A + (size_t)(cc * 2 + part) * M_ * NPIX_
                         + (size_t)(m0 + r) * NPIX_ + y0 + q * 8);
            } else {
                int dch = c - 1024;
                int x = dch >> 3, q = dch & 7;
                cp16(base + A_BUF + x * ROWB + q * 16,
                     gB + (size_t)x * KTOT + s * KSTAGE + q * 8);
            }
        }
        cp_commit();
    };

    float d[64];
#pragma unroll
    for (int i = 0; i < 64; i++) d[i] = 0.f;

    issue(0, 0);
    for (int s = 0; s < NSTG; s++) {
        const int p = s & 1;
        if (s < NSTG - 1) { issue(1 - p, s + 1); cp_wait<1>(); }
        else              { cp_wait<0>(); }
        __syncthreads();

        const char* buf = sm + p * STAGEB;
        const char* abase = buf + comp * (MT * ROWB) + (mw * 32 + rq) * ROWB + qk * 4;
        const char* bbase = buf + A_BUF + (xw * 64 + rq) * ROWB + qk * 4;
#pragma unroll
        for (int ks = 0; ks < 4; ks++) {
            uint32_t a[2][4];
#pragma unroll
            for (int mt2 = 0; mt2 < 2; mt2++) {
                const char* ap = abase + mt2 * (16 * ROWB) + ks * 32;
                a[mt2][0] = *(const uint32_t*)(ap);
                a[mt2][1] = *(const uint32_t*)(ap + 8 * ROWB);
                a[mt2][2] = *(const uint32_t*)(ap + 16);
                a[mt2][3] = *(const uint32_t*)(ap + 8 * ROWB + 16);
            }
#pragma unroll
            for (int nt = 0; nt < 8; nt++) {
                const char* bp = bbase + nt * (8 * ROWB) + ks * 32;
                uint32_t b0 = *(const uint32_t*)(bp);
                uint32_t b1 = *(const uint32_t*)(bp + 16);
                mma_bf16(d + (0 * 8 + nt) * 4, a[0], b0, b1);
                mma_bf16(d + (1 * 8 + nt) * 4, a[1], b0, b1);
            }
        }
        __syncthreads();
    }

    // ---- epilogue: Eu-weighted x-reduction ----
    const float2* EuC = (const float2*)(sm + SM_EUC);
    const float2* EuF = (const float2*)(sm + SM_EUF);
    float2* part = (float2*)(sm + SM_PART);

    float S[2][2][2] = {};
#pragma unroll
    for (int mt2 = 0; mt2 < 2; mt2++) {
#pragma unroll
        for (int nt = 0; nt < 8; nt++) {
            const int xbase = xw * 64 + nt * 8;
            const int jc = xbase >> 4;
            const int jf = (xbase & 15) + qk * 2;
#pragma unroll
            for (int rh = 0; rh < 2; rh++) {
                const int mloc = mw * 32 + mt2 * 16 + rq + rh * 8;
                float2 C  = EuC[mloc * 16 + jc];
                float2 F0 = EuF[mloc * 16 + jf];
                float2 F1 = EuF[mloc * 16 + jf + 1];
                float er0 = C.x * F0.x - C.y * F0.y, ei0 = C.x * F0.y + C.y * F0.x;
                float er1 = C.x * F1.x - C.y * F1.y, ei1 = C.x * F1.y + C.y * F1.x;
                float v0 = d[(mt2 * 8 + nt) * 4 + rh * 2 + 0];
                float v1 = d[(mt2 * 8 + nt) * 4 + rh * 2 + 1];
                S[mt2][rh][0] = fmaf(v0, er0, fmaf(v1, er1, S[mt2][rh][0]));
                S[mt2][rh][1] = fmaf(v0, ei0, fmaf(v1, ei1, S[mt2][rh][1]));
            }
        }
    }
#pragma unroll
    for (int mt2 = 0; mt2 < 2; mt2++)
#pragma unroll
        for (int rh = 0; rh < 2; rh++)
#pragma unroll
            for (int e = 0; e < 2; e++) {
                S[mt2][rh][e] += __shfl_xor_sync(0xFFFFFFFFu, S[mt2][rh][e], 1);
                S[mt2][rh][e] += __shfl_xor_sync(0xFFFFFFFFu, S[mt2][rh][e], 2);
            }
    if (qk == 0) {
#pragma unroll
        for (int mt2 = 0; mt2 < 2; mt2++)
#pragma unroll
            for (int rh = 0; rh < 2; rh++) {
                const int mloc = mw * 32 + mt2 * 16 + rq + rh * 8;
                part[(comp * 4 + xw) * 64 + mloc] = make_float2(S[mt2][rh][0], S[mt2][rh][1]);
            }
    }
    __syncthreads();

    if (t < MT) {
        float kr = 0.f, ki = 0.f;
#pragma unroll
        for (int x = 0; x < 4; x++) {
            float2 s0 = part[(0 * 4 + x) * 64 + t];   // re-plane: (Σ tr·er, Σ tr·ei)
            float2 s1 = part[(1 * 4 + x) * 64 + t];   // im-plane: (Σ ti·er, Σ ti·ei)
            kr += s0.x - s1.y;
            ki += s0.y + s1.x;
        }
        const int m = m0 + t;
        float p0 = pulse[m], p1 = pulse[M_ + m];
        float vr = kr * p0 - ki * p1;
        float vi = kr * p1 + ki * p0;
        out[(size_t)b * 2 * M_ + m]       = vr;
        out[(size_t)b * 2 * M_ + M_ + m]  = vi;
        out[OFF_AMP + (size_t)b * M_ + m] = sqrtf(vr * vr + vi * vi + EPSF);
    }
}

// ---------------- kernel 4: closure phases ----------------
__global__ void k_cphase(const float* __restrict__ vis, const float* __restrict__ sign,
                         const int* __restrict__ ind, float* __restrict__ out) {
    int idx = blockIdx.x * blockDim.x + threadIdx.x;
    if (idx >= B_ * NCP_) return;
    const int n = idx % NCP_;
    const int b = idx / NCP_;
    const size_t vb = (size_t)b * 2 * M_;
    float s = 0.f;
#pragma unroll
    for (int k = 0; k < 3; k++) {
        int i = ind[k * NCP_ + n];
        s += sign[k * NCP_ + n] * atan2f(vis[vb + M_ + i], vis[vb + i]);
    }
    out[OFF_CPH + idx] = s * 57.29577951308232f;
}

// ---------------- kernel 5: log closure amplitudes ----------------
__global__ void k_logcamp(const float* __restrict__ vis, const int* __restrict__ ind,
                          float* __restrict__ out) {
    int idx = blockIdx.x * blockDim.x + threadIdx.x;
    if (idx >= B_ * NCA_) return;
    const int n = idx % NCA_;
    const int b = idx / NCA_;
    const size_t vb = (size_t)b * 2 * M_;
    float v = 0.f;
#pragma unroll
    for (int k = 0; k < 4; k++) {
        int i = ind[k * NCA_ + n];
        float re = vis[vb + i];
        float im = vis[vb + M_ + i];
        float la = 0.5f * logf(re * re + im * im + EPSF);
        v += (k < 2) ? la : -la;
    }
    out[OFF_LC + idx] = v;
}

extern "C" void kernel_launch(void* const* d_in, const int* in_sizes, int n_in,
                              void* d_out, int out_size) {
    const float* images = (const float*)d_in[0];
    const float* ktraj  = (const float*)d_in[1];
    const float* pulse  = (const float*)d_in[2];
    const float* csign  = (const float*)d_in[3];
    const int*   cind   = (const int*)d_in[4];
    const int*   qind   = (const int*)d_in[5];
    float* out = (float*)d_out;

    cudaFuncSetAttribute(k_main, cudaFuncAttributeMaxDynamicSharedMemorySize, SM_TOTAL);

    const int ntab = M_ * NPIX_ + M_ * 32;
    k_tables<<<(ntab + 255) / 256, 256>>>(ktraj);

    dim3 gs(NPIX_ / 32, NPIX_ / 32, B_);
    k_split<<<gs, dim3(32, 8)>>>(images);

    k_main<<<dim3(M_ / MT, B_), 512, SM_TOTAL>>>(pulse, out);

    k_cphase<<<(B_ * NCP_ + 255) / 256, 256>>>(out, csign, cind, out);
    k_logcamp<<<(B_ * NCA_ + 255) / 256, 256>>>(out, qind, out);
}

// round 6
// speedup vs baseline: 2.0023x; 1.1400x over previous
#include <cuda_runtime.h>
#include <cuda_bf16.h>
#include <math.h>
#include <stdint.h>

// Problem constants
#define B_    8
#define NPIX_ 256
#define M_    8192
#define NCP_  24576
#define NCA_  24576
#define EPSF  1e-16f

// Output layout: vis(B,2,M), visamp(B,M), cphase(B,NCP), logcamp(B,NCA)
#define OFF_AMP (B_*2*M_)
#define OFF_CPH (OFF_AMP + B_*M_)
#define OFF_LC  (OFF_CPH + B_*NCP_)

// GEMM config
#define MT      64           // m-tile
#define KSEG    256
#define KTOT    768          // split-3: A[hi|lo|hi] * B[hi|hi|lo]
#define KSTAGE  64
#define NSTG    12

// Device-global operands (no cudaMalloc allowed)
__device__ __nv_bfloat16 g_A[4 * M_ * NPIX_];      // [comp][part][m][y]
__device__ __nv_bfloat16 g_B[B_ * NPIX_ * KTOT];   // [b][x][k]
__device__ float2 g_EuCF[M_ * 32];                 // coarse/fine Eu phasors

// SMEM: 128B rows, XOR-swizzled 16B chunks (chunk ^= row&7) -> conflict-free LDSM
#define A_BUF   (2 * MT * 128)             // 16384 (2 comps)
#define B_BUF   (NPIX_ * 128)              // 32768
#define STAGEB  (A_BUF + B_BUF)            // 49152
#define SM_EUC  (2 * STAGEB)               // 98304
#define SM_EUF  (SM_EUC + 8192)            // 106496
#define SM_PART (SM_EUF + 8192)            // 114688
#define SM_TOTAL (SM_PART + 4096)          // 118784

// ---------------- helpers ----------------
__device__ __forceinline__ uint32_t smem_u32(const void* p) {
    uint32_t a;
    asm("{ .reg .u64 t; cvta.to.shared.u64 t, %1; cvt.u32.u64 %0, t; }" : "=r"(a) : "l"(p));
    return a;
}
__device__ __forceinline__ void cp16(uint32_t dst, const void* src) {
    asm volatile("cp.async.cg.shared.global [%0], [%1], 16;" :: "r"(dst), "l"(src));
}
__device__ __forceinline__ void cp_commit() { asm volatile("cp.async.commit_group;" ::: "memory"); }
template <int N> __device__ __forceinline__ void cp_wait() {
    asm volatile("cp.async.wait_group %0;" :: "n"(N) : "memory");
}
__device__ __forceinline__ void mma_bf16(float* dd, const uint32_t* a, uint32_t b0, uint32_t b1) {
    asm volatile(
        "mma.sync.aligned.m16n8k16.row.col.f32.bf16.bf16.f32 "
        "{%0,%1,%2,%3}, {%4,%5,%6,%7}, {%8,%9}, {%0,%1,%2,%3};"
        : "+f"(dd[0]), "+f"(dd[1]), "+f"(dd[2]), "+f"(dd[3])
        : "r"(a[0]), "r"(a[1]), "r"(a[2]), "r"(a[3]), "r"(b0), "r"(b1));
}
__device__ __forceinline__ void ldsm4(uint32_t& r0, uint32_t& r1, uint32_t& r2, uint32_t& r3,
                                      uint32_t addr) {
    asm volatile("ldmatrix.sync.aligned.m8n8.x4.shared.b16 {%0,%1,%2,%3}, [%4];"
                 : "=r"(r0), "=r"(r1), "=r"(r2), "=r"(r3) : "r"(addr));
}

// ---------------- kernel 1: phase tables + Ev bf16 split planes ----------------
__global__ void k_tables(const float* __restrict__ ktraj) {
    int idx = blockIdx.x * blockDim.x + threadIdx.x;
    if (idx < M_ * NPIX_) {
        int m = idx >> 8, y = idx & 255;
        float s, c;
        sincosf(ktraj[m] * (float)(y - NPIX_ / 2), &s, &c);    // kv
        float re = c, im = -s;
        __nv_bfloat16 rh = __float2bfloat16(re);
        __nv_bfloat16 rl = __float2bfloat16(re - __bfloat162float(rh));
        __nv_bfloat16 ih = __float2bfloat16(im);
        __nv_bfloat16 il = __float2bfloat16(im - __bfloat162float(ih));
        g_A[0 * M_ * NPIX_ + idx] = rh;
        g_A[1 * M_ * NPIX_ + idx] = rl;
        g_A[2 * M_ * NPIX_ + idx] = ih;
        g_A[3 * M_ * NPIX_ + idx] = il;
        return;
    }
    idx -= M_ * NPIX_;
    if (idx < M_ * 32) {
        int m = idx >> 5, j = idx & 31;
        float ku = ktraj[M_ + m];
        float ang = (j < 16) ? ku * (float)(16 * j - 128) : ku * (float)(j - 16);
        float s, c;
        sincosf(ang, &s, &c);
        g_EuCF[idx] = make_float2(c, -s);
    }
}

// ---------------- kernel 2: img -> transposed split B ----------------
__global__ void k_split(const float* __restrict__ img) {
    __shared__ float tbuf[32][33];
    const int b = blockIdx.z, x0 = blockIdx.x * 32, y0 = blockIdx.y * 32;
    const int tx = threadIdx.x, ty = threadIdx.y;    // 32 x 8
    const float* ib = img + (size_t)b * NPIX_ * NPIX_;
#pragma unroll
    for (int r = 0; r < 4; r++)
        tbuf[ty + 8 * r][tx] = ib[(y0 + ty + 8 * r) * NPIX_ + x0 + tx];
    __syncthreads();
    __nv_bfloat16* ob = g_B + (size_t)b * NPIX_ * KTOT;
#pragma unroll
    for (int r = 0; r < 4; r++) {
        int x = x0 + ty + 8 * r;
        int y = y0 + tx;
        float v = tbuf[tx][ty + 8 * r];
        __nv_bfloat16 hi = __float2bfloat16(v);
        __nv_bfloat16 lo = __float2bfloat16(v - __bfloat162float(hi));
        __nv_bfloat16* row = ob + (size_t)x * KTOT;
        row[y] = hi;
        row[KSEG + y] = hi;
        row[2 * KSEG + y] = lo;
    }
}

// ---------------- kernel 3: HMMA DFT + fused epilogue ----------------
// 512 threads = 16 warps: comp = wid&1, xw = (wid>>1)&3, mw = wid>>3
// warp tile: 32m x 64x, one complex component. Accum: 64 f32/thread.
__global__ void __launch_bounds__(512, 1) k_main(const float* __restrict__ pulse,
                                                 float* __restrict__ out) {
    extern __shared__ char sm[];
    const uint32_t smb = smem_u32(sm);
    const int t = threadIdx.x;
    const int m0 = blockIdx.x * MT;
    const int b  = blockIdx.y;
    const int wid = t >> 5, lane = t & 31;
    const int comp = wid & 1, xw = (wid >> 1) & 3, mw = wid >> 3;
    const int rq = lane >> 2, qk = lane & 3;

    // Stage Eu tables (region disjoint from K-stage buffers)
    for (int i = t; i < MT * 16; i += 512) {
        int m = i >> 4, j = i & 15;
        ((float2*)(sm + SM_EUC))[i] = g_EuCF[(size_t)(m0 + m) * 32 + j];
        ((float2*)(sm + SM_EUF))[i] = g_EuCF[(size_t)(m0 + m) * 32 + 16 + j];
    }

    const __nv_bfloat16* gB = g_B + (size_t)b * NPIX_ * KTOT;

    // ---- cp.async stage issue: 3072 x 16B chunks, 6 per thread, XOR-swizzled dest ----
    auto issue = [&](int p, int s) {
        const int seg = s >> 2;
        const int y0  = (s & 3) * KSTAGE;
        const int part = (seg == 1) ? 1 : 0;
        const uint32_t base = smb + p * STAGEB;
#pragma unroll
        for (int it = 0; it < 6; it++) {
            int c = t + it * 512;
            if (c < 1024) {
                int cc = c >> 9, r = (c >> 3) & 63, q = c & 7;
                cp16(base + cc * (MT * 128) + r * 128 + ((q ^ (r & 7)) << 4),
                     g_A + (size_t)(cc * 2 + part) * M_ * NPIX_
                         + (size_t)(m0 + r) * NPIX_ + y0 + q * 8);
            } else {
                int dch = c - 1024;
                int x = dch >> 3, q = dch & 7;
                cp16(base + A_BUF + x * 128 + ((q ^ (x & 7)) << 4),
                     gB + (size_t)x * KTOT + s * KSTAGE + q * 8);
            }
        }
        cp_commit();
    };

    float d[64];
#pragma unroll
    for (int i = 0; i < 64; i++) d[i] = 0.f;

    // ldmatrix per-lane row bases (row&7 == lane&7 for all tiles -> one chunk offset)
    const int l15 = lane & 15;
    const int hi  = (lane >> 4) & 1;
    const int arx = l15 & 7;
    const uint32_t aRow0 = comp * (MT * 128) + (mw * 32 + l15) * 128;        // + mt2*2048
    const uint32_t bRow0 = A_BUF + (xw * 64 + l15) * 128;                    // + np*2048

    issue(0, 0);
    for (int s = 0; s < NSTG; s++) {
        const int p = s & 1;
        if (s < NSTG - 1) { issue(1 - p, s + 1); cp_wait<1>(); }
        else              { cp_wait<0>(); }
        __syncthreads();

        const uint32_t buf = smb + p * STAGEB;
#pragma unroll
        for (int ks = 0; ks < 4; ks++) {
            const uint32_t cx = (uint32_t)(((ks * 2 + hi) ^ arx) << 4);
            uint32_t a[2][4];
            ldsm4(a[0][0], a[0][1], a[0][2], a[0][3], buf + aRow0 + cx);
            ldsm4(a[1][0], a[1][1], a[1][2], a[1][3], buf + aRow0 + 2048 + cx);
#pragma unroll
            for (int np = 0; np < 4; np++) {
                uint32_t b0, b1, b2, b3;   // b0/b2: n-tile np*2, b1/b3: n-tile np*2+1
                ldsm4(b0, b1, b2, b3, buf + bRow0 + np * 2048 + cx);
                mma_bf16(d + (0 * 8 + np * 2 + 0) * 4, a[0], b0, b2);
                mma_bf16(d + (1 * 8 + np * 2 + 0) * 4, a[1], b0, b2);
                mma_bf16(d + (0 * 8 + np * 2 + 1) * 4, a[0], b1, b3);
                mma_bf16(d + (1 * 8 + np * 2 + 1) * 4, a[1], b1, b3);
            }
        }
        __syncthreads();
    }

    // ---- epilogue: Eu-weighted x-reduction ----
    const float2* EuC = (const float2*)(sm + SM_EUC);
    const float2* EuF = (const float2*)(sm + SM_EUF);
    float2* part = (float2*)(sm + SM_PART);

    float S[2][2][2] = {};
#pragma unroll
    for (int mt2 = 0; mt2 < 2; mt2++) {
#pragma unroll
        for (int nt = 0; nt < 8; nt++) {
            const int xbase = xw * 64 + nt * 8;
            const int jc = xbase >> 4;
            const int jf = (xbase & 15) + qk * 2;
#pragma unroll
            for (int rh = 0; rh < 2; rh++) {
                const int mloc = mw * 32 + mt2 * 16 + rq + rh * 8;
                float2 C  = EuC[mloc * 16 + jc];
                float2 F0 = EuF[mloc * 16 + jf];
                float2 F1 = EuF[mloc * 16 + jf + 1];
                float er0 = C.x * F0.x - C.y * F0.y, ei0 = C.x * F0.y + C.y * F0.x;
                float er1 = C.x * F1.x - C.y * F1.y, ei1 = C.x * F1.y + C.y * F1.x;
                float v0 = d[(mt2 * 8 + nt) * 4 + rh * 2 + 0];
                float v1 = d[(mt2 * 8 + nt) * 4 + rh * 2 + 1];
                S[mt2][rh][0] = fmaf(v0, er0, fmaf(v1, er1, S[mt2][rh][0]));
                S[mt2][rh][1] = fmaf(v0, ei0, fmaf(v1, ei1, S[mt2][rh][1]));
            }
        }
    }
#pragma unroll
    for (int mt2 = 0; mt2 < 2; mt2++)
#pragma unroll
        for (int rh = 0; rh < 2; rh++)
#pragma unroll
            for (int e = 0; e < 2; e++) {
                S[mt2][rh][e] += __shfl_xor_sync(0xFFFFFFFFu, S[mt2][rh][e], 1);
                S[mt2][rh][e] += __shfl_xor_sync(0xFFFFFFFFu, S[mt2][rh][e], 2);
            }
    if (qk == 0) {
#pragma unroll
        for (int mt2 = 0; mt2 < 2; mt2++)
#pragma unroll
            for (int rh = 0; rh < 2; rh++) {
                const int mloc = mw * 32 + mt2 * 16 + rq + rh * 8;
                part[(comp * 4 + xw) * 64 + mloc] = make_float2(S[mt2][rh][0], S[mt2][rh][1]);
            }
    }
    __syncthreads();

    if (t < MT) {
        float kr = 0.f, ki = 0.f;
#pragma unroll
        for (int x = 0; x < 4; x++) {
            float2 s0 = part[(0 * 4 + x) * 64 + t];   // re-plane
            float2 s1 = part[(1 * 4 + x) * 64 + t];   // im-plane
            kr += s0.x - s1.y;
            ki += s0.y + s1.x;
        }
        const int m = m0 + t;
        float p0 = pulse[m], p1 = pulse[M_ + m];
        float vr = kr * p0 - ki * p1;
        float vi = kr * p1 + ki * p0;
        out[(size_t)b * 2 * M_ + m]       = vr;
        out[(size_t)b * 2 * M_ + M_ + m]  = vi;
        out[OFF_AMP + (size_t)b * M_ + m] = sqrtf(vr * vr + vi * vi + EPSF);
    }
}

// ---------------- kernel 4: fused closure phases + log closure amplitudes ----------------
__global__ void k_closures(const float* __restrict__ vis, const float* __restrict__ sign,
                           const int* __restrict__ cind, const int* __restrict__ qind,
                           float* __restrict__ out) {
    int idx = blockIdx.x * blockDim.x + threadIdx.x;
    if (idx < B_ * NCP_) {
        const int n = idx % NCP_;
        const int b = idx / NCP_;
        const size_t vb = (size_t)b * 2 * M_;
        float s = 0.f;
#pragma unroll
        for (int k = 0; k < 3; k++) {
            int i = cind[k * NCP_ + n];
            s += sign[k * NCP_ + n] * atan2f(vis[vb + M_ + i], vis[vb + i]);
        }
        out[OFF_CPH + idx] = s * 57.29577951308232f;
        return;
    }
    idx -= B_ * NCP_;
    if (idx < B_ * NCA_) {
        const int n = idx % NCA_;
        const int b = idx / NCA_;
        const size_t vb = (size_t)b * 2 * M_;
        float v = 0.f;
#pragma unroll
        for (int k = 0; k < 4; k++) {
            int i = qind[k * NCA_ + n];
            float re = vis[vb + i];
            float im = vis[vb + M_ + i];
            float la = 0.5f * logf(re * re + im * im + EPSF);
            v += (k < 2) ? la : -la;
        }
        out[OFF_LC + idx] = v;
    }
}

extern "C" void kernel_launch(void* const* d_in, const int* in_sizes, int n_in,
                              void* d_out, int out_size) {
    const float* images = (const float*)d_in[0];
    const float* ktraj  = (const float*)d_in[1];
    const float* pulse  = (const float*)d_in[2];
    const float* csign  = (const float*)d_in[3];
    const int*   cind   = (const int*)d_in[4];
    const int*   qind   = (const int*)d_in[5];
    float* out = (float*)d_out;

    cudaFuncSetAttribute(k_main, cudaFuncAttributeMaxDynamicSharedMemorySize, SM_TOTAL);

    const int ntab = M_ * NPIX_ + M_ * 32;
    k_tables<<<(ntab + 255) / 256, 256>>>(ktraj);

    dim3 gs(NPIX_ / 32, NPIX_ / 32, B_);
    k_split<<<gs, dim3(32, 8)>>>(images);

    k_main<<<dim3(M_ / MT, B_), 512, SM_TOTAL>>>(pulse, out);

    k_closures<<<(B_ * (NCP_ + NCA_) + 255) / 256, 256>>>(out, csign, cind, qind, out);
}